// round 6
// baseline (speedup 1.0000x reference)
#include <cuda_runtime.h>
#include <cuda_bf16.h>

// SegEncodeLoss: per 32x32 block multi-hot class presence, BCE-with-logits vs preds, mean.
// Shapes fixed: B=32, H=W=1024, G=32, C=19 -> n_blocks = 32768.
// Persistent single-wave grid (148 SMs x 8 CTAs = 1184), warp grid-strides over
// blocks; reductions deferred to once-per-warp. Last CTA finalizes and resets
// device accumulators (graph-replay determinism).

#define NUM_C   19
#define GSZ     32
#define BATCH   32
#define HDIM    1024
#define WDIM    1024
#define NBLK    (BATCH * (HDIM / GSZ) * (WDIM / GSZ))   // 32768
#define WARPS_PER_CTA 8
#define NCTA_P  1184                                     // 148 SMs * 8 resident CTAs
#define TOT_WARPS (NCTA_P * WARPS_PER_CTA)               // 9472

__device__ double       g_acc;    // zero-init at module load; last CTA re-zeros
__device__ unsigned int g_count;  // ditto

__global__ __launch_bounds__(WARPS_PER_CTA * 32)
void seg_loss_k(const float* __restrict__ preds, const int* __restrict__ targets,
                float* __restrict__ out) {
    __shared__ float s_acc;
    const int tid  = threadIdx.x;
    if (tid == 0) s_acc = 0.0f;
    __syncthreads();

    const int lane = tid & 31;
    const int wgid = blockIdx.x * WARPS_PER_CTA + (tid >> 5);

    // lane -> (subrow = lane/8, 16B column group = lane%8); 8 iters cover 32x32.
    const int r0 = lane >> 3;
    const int cg = lane & 7;

    float val = 0.0f;

    for (int n = wgid; n < NBLK; n += TOT_WARPS) {
        // n = b*1024 + hb*32 + wb (matches reference reshape/transpose)
        const int b  = n >> 10;
        const int hb = (n >> 5) & 31;
        const int wb = n & 31;

        const int4* base = (const int4*)(targets
                            + ((size_t)b * HDIM + (size_t)hb * GSZ) * WDIM
                            + (size_t)wb * GSZ);

        unsigned mask = 0u;
        #pragma unroll
        for (int it = 0; it < 8; ++it) {
            const int row = it * 4 + r0;
            int4 v = __ldcs(&base[row * (WDIM / 4) + cg]);   // read-once stream
            mask |= (1u << v.x) | (1u << v.y) | (1u << v.z) | (1u << v.w);
        }
        mask = __reduce_or_sync(0xffffffffu, mask);

        // BCE-with-logits: loss = softplus(x) - t*x (stable softplus).
        // Lane c (< 19) owns class c; accumulate locally, reduce after the loop.
        if (lane < NUM_C) {
            const float x  = __ldcs(&preds[n * NUM_C + lane]);
            const float sp = fmaxf(x, 0.0f) + log1pf(__expf(-fabsf(x)));
            val += sp - (((mask >> lane) & 1u) ? x : 0.0f);
        }
    }

    // Once-per-warp reduction
    #pragma unroll
    for (int off = 16; off; off >>= 1)
        val += __shfl_down_sync(0xffffffffu, val, off);
    if (lane == 0) atomicAdd(&s_acc, val);

    __syncthreads();
    if (tid == 0) {
        atomicAdd(&g_acc, (double)s_acc);
        __threadfence();
        unsigned ticket = atomicAdd(&g_count, 1u);
        if (ticket == NCTA_P - 1) {
            out[0] = (float)(g_acc / (double)((long long)NBLK * NUM_C));
            g_acc   = 0.0;      // restore state for next graph replay
            g_count = 0u;
        }
    }
}

extern "C" void kernel_launch(void* const* d_in, const int* in_sizes, int n_in,
                              void* d_out, int out_size) {
    const float* preds   = (const float*)d_in[0];
    const int*   targets = (const int*)d_in[1];
    // d_in[2] = grid_size (fixed at 32; shapes hardcoded)

    seg_loss_k<<<NCTA_P, WARPS_PER_CTA * 32>>>(preds, targets, (float*)d_out);
}